// round 6
// baseline (speedup 1.0000x reference)
#include <cuda_runtime.h>

// RGBuvHistBlock: x [8,3,256,256] f32 in [0,1]; bin_vals [64] = linspace(-1,1).
// hist[nc][b] = sum_p exp(-((2x-1)-b)^2/(2*0.02^2)), normalized per nc.
//
// R6: R5 windowed scatter + occupancy fix. R5 ran 384 blocks = 2.6 warps/SMSP,
// issue=42% (LDS-latency exposed on the RMW chain). SPLITS 16->32 doubles
// resident warps (5.2/SMSP); pipe floors sit at ~4.6k cyc/SM (LSU == MUFU).

#define NC_TOTAL   24
#define PIX_PER_NC 65536
#define HB         64
#define SPLITS     32
#define CHUNK      2048          // pixels per block
#define NT         128           // threads per block
#define WIN        7             // window bins (+-3)

// s = SA*(2x-1); weight = 2^{-(s-t)^2}; SA = sqrt(1250*log2(e))
#define SA   42.46608994f
#define SA2  84.93217988f
#define DS   1.34812984f         // SA * 2/63 (scaled bin spacing)

__device__ float    g_part[NC_TOTAL * SPLITS * HB];
__device__ unsigned g_cnt[NC_TOTAL];

__device__ __forceinline__ float ex2f(float a) {
    float r;
    asm("ex2.approx.ftz.f32 %0, %1;" : "=f"(r) : "f"(a));
    return r;
}

__global__ __launch_bounds__(NT) void hist_fused_kernel(
    const float* __restrict__ x, const float* __restrict__ bin_vals,
    float* __restrict__ out)
{
    const int nc    = blockIdx.y;
    const int split = blockIdx.x;
    const int tid   = threadIdx.x;

    __shared__ float hist[HB * NT];     // 32KB per-thread private hists
    __shared__ float racc[NT];
    __shared__ float ws[2];
    __shared__ int   slast;

    // Zero private hists (16 STS.128 per thread).
    {
        float4* hz = reinterpret_cast<float4*>(hist);
#pragma unroll
        for (int i = 0; i < (HB * NT / 4) / NT; ++i)
            hz[tid + i * NT] = make_float4(0.f, 0.f, 0.f, 0.f);
    }
    __syncthreads();

    const float4* xp = reinterpret_cast<const float4*>(
        x + (size_t)nc * PIX_PER_NC + (size_t)split * CHUNK);

#pragma unroll
    for (int it = 0; it < CHUNK / (4 * NT); ++it) {
        float4 v = xp[tid + it * NT];
        float pv[4] = {v.x, v.y, v.z, v.w};
#pragma unroll
        for (int p = 0; p < 4; ++p) {
            float vf = pv[p];
            float s  = fmaf(vf, SA2, -SA);          // scaled coordinate
            int j0   = __float2int_rn(vf * 63.0f);
            int jc   = min(max(j0, 3), 60);         // window center, fully in-range
            float a  = fmaf((float)(jc - 3), -DS, s + SA);  // d at k=0

            float h[WIN], w[WIN];
            const int base = (jc - 3) * NT + tid;
#pragma unroll
            for (int k = 0; k < WIN; ++k)           // 7 loads first (distinct cells)
                h[k] = hist[base + k * NT];
#pragma unroll
            for (int k = 0; k < WIN; ++k) {
                float d = fmaf((float)k, -DS, a);
                w[k] = ex2f(-d * d);
            }
#pragma unroll
            for (int k = 0; k < WIN; ++k)           // then 7 stores
                hist[base + k * NT] = h[k] + w[k];
        }
    }
    __syncthreads();

    // Block reduce: bin b = tid&63, half = tid>>6. Thread (b,0) sums cells
    // {b..b+63}, thread (b,1) sums {b+64..b+127} (mod 128): disjoint, complete,
    // conflict-free (cell mod 32 distinct within each warp).
    {
        const int b    = tid & (HB - 1);
        const int half = tid >> 6;
        float acc = 0.0f;
        const float* hb = hist + b * NT;
#pragma unroll 8
        for (int i = 0; i < 64; ++i)
            acc += hb[(half * 64 + i + b) & (NT - 1)];
        racc[tid] = acc;
    }
    __syncthreads();

    if (tid < HB)
        g_part[((size_t)nc * SPLITS + split) * HB + tid] = racc[tid] + racc[tid + 64];
    __syncthreads();

    // Last block per nc reduces + normalizes.
    if (tid == 0) {
        __threadfence();
        unsigned old = atomicAdd(&g_cnt[nc], 1u);
        slast = (old == SPLITS - 1);
    }
    __syncthreads();
    if (!slast) return;
    __threadfence();

    float bsum = 0.0f;
    if (tid < HB) {
        const float* p = g_part + (size_t)nc * SPLITS * HB + tid;
#pragma unroll
        for (int sp = 0; sp < SPLITS; ++sp)
            bsum += p[(size_t)sp * HB];
    }
    float v = (tid < HB) ? bsum : 0.0f;
    float r = v;
#pragma unroll
    for (int o = 16; o; o >>= 1) r += __shfl_xor_sync(0xffffffffu, r, o);
    if (tid == 0)  ws[0] = r;
    if (tid == 32) ws[1] = r;
    __syncthreads();
    float tot = ws[0] + ws[1];

    if (tid < HB)
        out[nc * HB + tid] = v / (tot + 1e-8f);

    if (tid == 0) g_cnt[nc] = 0;   // reset for next graph replay
}

extern "C" void kernel_launch(void* const* d_in, const int* in_sizes, int n_in,
                              void* d_out, int out_size) {
    const float* x        = (const float*)d_in[0];
    const float* bin_vals = (const float*)d_in[1];
    float* out            = (float*)d_out;

    dim3 grid(SPLITS, NC_TOTAL);
    hist_fused_kernel<<<grid, NT>>>(x, bin_vals, out);
}